// round 15
// baseline (speedup 1.0000x reference)
#include <cuda_runtime.h>
#include <cfloat>

#define BB 8
#define NN 2048
#define KNBR 32
#define NPTS (BB*NN)
#define NBLK (NN/128)           // 16 tiles per dim
#define NPAIR (NBLK*(NBLK+1)/2) // 136 upper-tri block pairs

typedef unsigned long long u64;

__device__ __forceinline__ u64 pack2(float lo, float hi) {
    u64 r;
    asm("mov.b64 %0, {%1, %2};" : "=l"(r) : "f"(lo), "f"(hi));
    return r;
}
__device__ __forceinline__ float2 unpack2(u64 v) {
    float2 f;
    asm("mov.b64 {%0, %1}, %2;" : "=f"(f.x), "=f"(f.y) : "l"(v));
    return f;
}
__device__ __forceinline__ void fma2(u64& d, u64 a, u64 b) {
    asm("fma.rn.f32x2 %0, %1, %2, %0;" : "+l"(d) : "l"(a), "l"(b));
}
__device__ __forceinline__ unsigned flipkey(float f) {
    unsigned b = __float_as_uint(f);
    return (b & 0x80000000u) ? ~b : (b | 0x80000000u);
}
__device__ __forceinline__ float4 max4(float4 a, float4 b) {
    return make_float4(fmaxf(a.x, b.x), fmaxf(a.y, b.y), fmaxf(a.z, b.z), fmaxf(a.w, b.w));
}

// ---------------- scratch (static device globals; no runtime alloc) ----------
__device__ unsigned g_keys[(size_t)NPTS * NN]; // 134MB pairwise keys (monotone map of d2)
__device__ float g_sq[NPTS];
__device__ int   g_idx[NPTS * KNBR];
__device__ float g_x1[NPTS * 64];
__device__ float g_x2[NPTS * 128];
__device__ float g_xc[NPTS * 192];
__device__ float g_qp[(size_t)NPTS * 1024];  // [q | p] per point, max 2*512
__device__ float g_wc[256 * 1024];           // 3 disjoint combined-weight slices

// ---------------- squared norms ----------------------------------------------
__global__ void sq_kernel(const float* __restrict__ X, float* __restrict__ sq, int C) {
    int i = blockIdx.x * blockDim.x + threadIdx.x;
    if (i < NPTS) {
        const float* r = X + (size_t)i * C;
        float s = 0.f;
        for (int c = 0; c < C; c++) s += r[c] * r[c];
        sq[i] = s;
    }
}

// ---------------- pairwise d2 keys, symmetric, FFMA2 inner loop ---------------
__global__ void __launch_bounds__(256, 2)
d2sym_kernel(const float* __restrict__ X, const float* __restrict__ sq,
             unsigned* __restrict__ keys, int C) {
    __shared__ __align__(16) float As[16][132];
    __shared__ __align__(16) float Bs[16][132];
    int b = blockIdx.y;
    int rem = blockIdx.x, bi = 0;
    while (rem >= NBLK - bi) { rem -= NBLK - bi; bi++; }
    int bj = bi + rem;
    int row0 = bi * 128, col0 = bj * 128;

    const float* Xb = X + (size_t)b * NN * C;
    int tid = threadIdx.x;
    int ty = tid >> 4, tx = tid & 15;
    u64 acc2[8][4];
#pragma unroll
    for (int i = 0; i < 8; i++)
#pragma unroll
        for (int j = 0; j < 4; j++) acc2[i][j] = 0ull;

    int kk = tid & 15, i0 = tid >> 4;

    if (C <= 16) {
        bool kin = (kk < C);
#pragma unroll
        for (int u = 0; u < 8; u++) {
            int i = i0 + (u << 4);
            As[kk][i] = kin ? Xb[(size_t)(row0 + i) * C + kk] : 0.f;
            Bs[kk][i] = kin ? Xb[(size_t)(col0 + i) * C + kk] : 0.f;
        }
        __syncthreads();
        for (int t = 0; t < C; t++) {
            float a[8], bv[8];
            *(float4*)&a[0]  = *(const float4*)&As[t][ty << 2];
            *(float4*)&a[4]  = *(const float4*)&As[t][64 + (ty << 2)];
            *(float4*)&bv[0] = *(const float4*)&Bs[t][tx << 2];
            *(float4*)&bv[4] = *(const float4*)&Bs[t][64 + (tx << 2)];
            u64 b2[4];
#pragma unroll
            for (int j = 0; j < 4; j++) b2[j] = pack2(bv[2 * j], bv[2 * j + 1]);
#pragma unroll
            for (int i = 0; i < 8; i++) {
                u64 a2 = pack2(a[i], a[i]);
#pragma unroll
                for (int j = 0; j < 4; j++) fma2(acc2[i][j], a2, b2[j]);
            }
        }
        __syncthreads();
    } else {
        for (int k0 = 0; k0 < C; k0 += 16) {
            int k = k0 + kk;
#pragma unroll
            for (int u = 0; u < 8; u++) {
                int i = i0 + (u << 4);
                As[kk][i] = Xb[(size_t)(row0 + i) * C + k];
                Bs[kk][i] = Xb[(size_t)(col0 + i) * C + k];
            }
            __syncthreads();
#pragma unroll
            for (int t = 0; t < 16; t++) {
                float a[8], bv[8];
                *(float4*)&a[0]  = *(const float4*)&As[t][ty << 2];
                *(float4*)&a[4]  = *(const float4*)&As[t][64 + (ty << 2)];
                *(float4*)&bv[0] = *(const float4*)&Bs[t][tx << 2];
                *(float4*)&bv[4] = *(const float4*)&Bs[t][64 + (tx << 2)];
                u64 b2[4];
#pragma unroll
                for (int j = 0; j < 4; j++) b2[j] = pack2(bv[2 * j], bv[2 * j + 1]);
#pragma unroll
                for (int i = 0; i < 8; i++) {
                    u64 a2 = pack2(a[i], a[i]);
#pragma unroll
                    for (int j = 0; j < 4; j++) fma2(acc2[i][j], a2, b2[j]);
                }
            }
            __syncthreads();
        }
    }

    unsigned kv[8][8];
#pragma unroll
    for (int i = 0; i < 8; i++) {
        int r = row0 + ((i < 4) ? ((ty << 2) + i) : (64 + (ty << 2) + i - 4));
        float sqr = sq[b * NN + r];
#pragma unroll
        for (int j = 0; j < 4; j++) {
            float2 f = unpack2(acc2[i][j]);
            int c0 = col0 + ((2*j < 4) ? ((tx << 2) + 2*j) : (64 + (tx << 2) + 2*j - 4));
            int c1 = col0 + ((2*j+1 < 4) ? ((tx << 2) + 2*j+1) : (64 + (tx << 2) + 2*j+1 - 4));
            float v0 = sqr + sq[b * NN + c0] - 2.f * f.x;
            float v1 = sqr + sq[b * NN + c1] - 2.f * f.y;
            if (r == c0) v0 = FLT_MAX;
            if (r == c1) v1 = FLT_MAX;
            kv[i][2*j]   = flipkey(v0);
            kv[i][2*j+1] = flipkey(v1);
        }
    }

    unsigned* kb = keys + (size_t)b * NN * NN;
#pragma unroll
    for (int i = 0; i < 8; i++) {
        int r = row0 + ((i < 4) ? ((ty << 2) + i) : (64 + (ty << 2) + i - 4));
        uint4 v0 = make_uint4(kv[i][0], kv[i][1], kv[i][2], kv[i][3]);
        uint4 v1 = make_uint4(kv[i][4], kv[i][5], kv[i][6], kv[i][7]);
        __stcs((uint4*)&kb[(size_t)r * NN + col0 + (tx << 2)],      v0);
        __stcs((uint4*)&kb[(size_t)r * NN + col0 + 64 + (tx << 2)], v1);
    }
    if (bi != bj) {
#pragma unroll
        for (int j = 0; j < 8; j++) {
            int c = col0 + ((j < 4) ? ((tx << 2) + j) : (64 + (tx << 2) + j - 4));
            uint4 lo = make_uint4(kv[0][j], kv[1][j], kv[2][j], kv[3][j]);
            uint4 hi = make_uint4(kv[4][j], kv[5][j], kv[6][j], kv[7][j]);
            __stcs((uint4*)&kb[(size_t)c * NN + row0 + (ty << 2)],      lo);
            __stcs((uint4*)&kb[(size_t)c * NN + row0 + 64 + (ty << 2)], hi);
        }
    }
}

// ---------------- top-K via 4-pass (8-bit) radix select ------------------------
__global__ void __launch_bounds__(256)
knn_kernel(const unsigned* __restrict__ keys_g, int* __restrict__ idxout) {
    __shared__ int hist[2048];      // 256 used as bins; full 2048 reused as tie buffer
    __shared__ int wsum[8], wsumex[8];
    __shared__ int ctrlB, ctrlBelow;
    __shared__ int cnt, eqcnt;

    int p = blockIdx.x;
    int t = threadIdx.x, lane = t & 31, wid = t >> 5;

    const uint4* row4 = (const uint4*)(keys_g + (size_t)p * NN);
    unsigned key[8];
#pragma unroll
    for (int u = 0; u < 2; u++) {
        uint4 f = __ldcs(&row4[t + (u << 8)]);
        key[u * 4 + 0] = f.x; key[u * 4 + 1] = f.y;
        key[u * 4 + 2] = f.z; key[u * 4 + 3] = f.w;
    }

    unsigned pval = 0, pmask = 0;
    int base = 0;
#pragma unroll
    for (int pass = 0; pass < 4; pass++) {
        const int shift = 24 - (pass << 3);
        hist[t] = 0;
        __syncthreads();
        if (pass == 0) {
#pragma unroll
            for (int e = 0; e < 8; e++) {
                int bin = key[e] >> 24;
                unsigned peers = __match_any_sync(0xffffffffu, bin);
                int leader = __ffs(peers) - 1;
                if (lane == leader) atomicAdd(&hist[bin], __popc(peers));
            }
        } else {
#pragma unroll
            for (int e = 0; e < 8; e++) {
                unsigned k = key[e];
                if ((k & pmask) == pval) atomicAdd(&hist[(k >> shift) & 255], 1);
            }
        }
        __syncthreads();
        int s = hist[t];
        int incl = s;
#pragma unroll
        for (int off = 1; off < 32; off <<= 1) {
            int n = __shfl_up_sync(0xffffffffu, incl, off);
            if (lane >= off) incl += n;
        }
        if (lane == 31) wsum[wid] = incl;
        __syncthreads();
        if (t == 0) {
            int run = 0;
            for (int w = 0; w < 8; w++) { wsumex[w] = run; run += wsum[w]; }
        }
        __syncthreads();
        int excl = wsumex[wid] + incl - s;
        int need = KNBR - base;
        if (excl < need && need <= excl + s) {
            ctrlB = t; ctrlBelow = excl;
        }
        __syncthreads();
        base += ctrlBelow;
        pval |= ((unsigned)ctrlB) << shift;
        pmask |= 255u << shift;
        __syncthreads();
    }

    const unsigned T = pval;
    if (t == 0) { cnt = 0; eqcnt = 0; }
    __syncthreads();
#pragma unroll
    for (int e = 0; e < 8; e++) {
        unsigned k = key[e];
        int i = (t << 2) + ((e >> 2) << 10) + (e & 3);
        if (k < T) {
            int pos = atomicAdd(&cnt, 1);
            idxout[p * KNBR + pos] = i;
        } else if (k == T) {
            int q = atomicAdd(&eqcnt, 1);
            hist[q] = i;
        }
    }
    __syncthreads();
    int c = cnt, E = eqcnt, tn = KNBR - c;
    if (E == tn) {
        for (int j = t; j < E; j += 256) idxout[p * KNBR + c + j] = hist[j];
    } else {
        for (int j = t; j < E; j += 256) {
            int mi = hist[j], r = 0;
            for (int q = 0; q < E; q++) r += (hist[q] < mi);
            if (r < tn) idxout[p * KNBR + c + r] = mi;
        }
    }
}

// ---------------- combined weight prep: wc = [Wb | Wa - Wb] -------------------
__global__ void prepw_kernel(const float* __restrict__ W, float* __restrict__ wc,
                             int C, int Cout) {
    int i = blockIdx.x * blockDim.x + threadIdx.x;
    if (i < C * Cout) {
        int c = i / Cout, d = i % Cout;
        float wa = W[c * Cout + d];
        float wb = W[(C + c) * Cout + d];
        wc[c * (2 * Cout) + d] = wb;
        wc[c * (2 * Cout) + Cout + d] = wa - wb;
    }
}

// ---------------- generic GEMM with FFMA2 inner loop ---------------------------
__global__ void __launch_bounds__(256, 2)
gemm_kernel(const float* __restrict__ A, const float* __restrict__ Bm,
            float* __restrict__ Cm, int Kd, int Nd) {
    __shared__ __align__(16) float As[16][132];
    __shared__ __align__(16) float Bs[16][132];
    int row0 = blockIdx.y * 128, col0 = blockIdx.x * 128;
    int tid = threadIdx.x;
    int ty = tid >> 4, tx = tid & 15;
    u64 acc2[8][4];
#pragma unroll
    for (int i = 0; i < 8; i++)
#pragma unroll
        for (int j = 0; j < 4; j++) acc2[i][j] = 0ull;

    int kk = tid & 15, i0 = tid >> 4;
    int j0 = tid & 127, kb = tid >> 7;

    for (int k0 = 0; k0 < Kd; k0 += 16) {
        int k = k0 + kk;
        bool kin = (k < Kd);
#pragma unroll
        for (int u = 0; u < 8; u++) {
            int i = i0 + (u << 4);
            As[kk][i] = kin ? A[(size_t)(row0 + i) * Kd + k] : 0.f;
        }
#pragma unroll
        for (int u = 0; u < 8; u++) {
            int kr = kb + (u << 1);
            int kg = k0 + kr;
            Bs[kr][j0] = (kg < Kd) ? Bm[(size_t)kg * Nd + col0 + j0] : 0.f;
        }
        __syncthreads();
#pragma unroll
        for (int t = 0; t < 16; t++) {
            float a[8], bv[8];
            *(float4*)&a[0]  = *(const float4*)&As[t][ty << 2];
            *(float4*)&a[4]  = *(const float4*)&As[t][64 + (ty << 2)];
            *(float4*)&bv[0] = *(const float4*)&Bs[t][tx << 2];
            *(float4*)&bv[4] = *(const float4*)&Bs[t][64 + (tx << 2)];
            u64 b2[4];
#pragma unroll
            for (int j = 0; j < 4; j++) b2[j] = pack2(bv[2 * j], bv[2 * j + 1]);
#pragma unroll
            for (int i = 0; i < 8; i++) {
                u64 a2 = pack2(a[i], a[i]);
#pragma unroll
                for (int j = 0; j < 4; j++) fma2(acc2[i][j], a2, b2[j]);
            }
        }
        __syncthreads();
    }
#pragma unroll
    for (int i = 0; i < 8; i++) {
        int r = row0 + ((i < 4) ? ((ty << 2) + i) : (64 + (ty << 2) + i - 4));
        float2 f0 = unpack2(acc2[i][0]), f1 = unpack2(acc2[i][1]);
        float2 f2 = unpack2(acc2[i][2]), f3 = unpack2(acc2[i][3]);
        float4 v0 = make_float4(f0.x, f0.y, f1.x, f1.y);
        float4 v1 = make_float4(f2.x, f2.y, f3.x, f3.y);
        *(float4*)&Cm[(size_t)r * Nd + col0 + (tx << 2)]      = v0;
        *(float4*)&Cm[(size_t)r * Nd + col0 + 64 + (tx << 2)] = v1;
    }
}

// ---------------- gather-max, smem-staged 8-channel slices ---------------------
// grid (Cout/8, BB), 256 threads, 64KB dynamic smem.
// Block stages the 8-channel q-slice of its batch (2048 pts x 32B, full-sector
// reads), then all neighbor maxes run from smem. All global accesses are >=32B
// contiguous per point -> no sector waste.
__global__ void __launch_bounds__(256)
gather_kernel(const float* __restrict__ qp, const int* __restrict__ idx,
              const float* __restrict__ bias, float* __restrict__ out,
              int Cout, int relu) {
    extern __shared__ __align__(16) float qs[];   // [NN][8]
    int s0 = blockIdx.x * 8;
    int b = blockIdx.y;
    int ld = 2 * Cout;
    size_t base = (size_t)b * NN;

    for (int i = threadIdx.x; i < NN * 2; i += 256) {
        int p = i >> 1, h = (i & 1) << 2;
        *(float4*)&qs[p * 8 + h] = *(const float4*)&qp[(base + p) * ld + s0 + h];
    }
    __syncthreads();

    float4 bb0 = *(const float4*)&bias[s0];
    float4 bb1 = *(const float4*)&bias[s0 + 4];
#pragma unroll
    for (int u = 0; u < NN / 256; u++) {
        int p = threadIdx.x + (u << 8);
        const int4* ip = (const int4*)(idx + (base + p) * KNBR);
        float4 m0 = make_float4(-FLT_MAX, -FLT_MAX, -FLT_MAX, -FLT_MAX);
        float4 m1 = m0;
#pragma unroll
        for (int w = 0; w < 8; w++) {
            int4 nb = ip[w];
            m0 = max4(m0, *(const float4*)&qs[nb.x * 8]);
            m1 = max4(m1, *(const float4*)&qs[nb.x * 8 + 4]);
            m0 = max4(m0, *(const float4*)&qs[nb.y * 8]);
            m1 = max4(m1, *(const float4*)&qs[nb.y * 8 + 4]);
            m0 = max4(m0, *(const float4*)&qs[nb.z * 8]);
            m1 = max4(m1, *(const float4*)&qs[nb.z * 8 + 4]);
            m0 = max4(m0, *(const float4*)&qs[nb.w * 8]);
            m1 = max4(m1, *(const float4*)&qs[nb.w * 8 + 4]);
        }
        float4 p0 = *(const float4*)&qp[(base + p) * ld + Cout + s0];
        float4 p1 = *(const float4*)&qp[(base + p) * ld + Cout + s0 + 4];
        float4 r0, r1;
        r0.x = p0.x + bb0.x + m0.x; r0.y = p0.y + bb0.y + m0.y;
        r0.z = p0.z + bb0.z + m0.z; r0.w = p0.w + bb0.w + m0.w;
        r1.x = p1.x + bb1.x + m1.x; r1.y = p1.y + bb1.y + m1.y;
        r1.z = p1.z + bb1.z + m1.z; r1.w = p1.w + bb1.w + m1.w;
        if (relu) {
            r0.x = fmaxf(r0.x, 0.f); r0.y = fmaxf(r0.y, 0.f);
            r0.z = fmaxf(r0.z, 0.f); r0.w = fmaxf(r0.w, 0.f);
            r1.x = fmaxf(r1.x, 0.f); r1.y = fmaxf(r1.y, 0.f);
            r1.z = fmaxf(r1.z, 0.f); r1.w = fmaxf(r1.w, 0.f);
        }
        *(float4*)&out[(base + p) * Cout + s0]     = r0;
        *(float4*)&out[(base + p) * Cout + s0 + 4] = r1;
    }
}

// ---------------- concat x1 | x2 (float4) --------------------------------------
__global__ void concat_kernel(const float* __restrict__ x1, const float* __restrict__ x2,
                              float* __restrict__ xc) {
    int i = blockIdx.x * blockDim.x + threadIdx.x;
    if (i < NPTS * 48) {
        int p = i / 48, c = i % 48;
        float4 v = (c < 16) ? ((const float4*)x1)[p * 16 + c]
                            : ((const float4*)x2)[p * 32 + (c - 16)];
        ((float4*)xc)[i] = v;
    }
}

// ---------------- launch (round-9 two-stream schedule) -------------------------
extern "C" void kernel_launch(void* const* d_in, const int* in_sizes, int n_in,
                              void* d_out, int out_size) {
    const float* x  = (const float*)d_in[0];
    const float* W1 = (const float*)d_in[1];
    const float* b1 = (const float*)d_in[2];
    const float* W2 = (const float*)d_in[3];
    const float* b2 = (const float*)d_in[4];
    const float* W3 = (const float*)d_in[5];
    const float* b3 = (const float*)d_in[6];
    float* out = (float*)d_out;

    float *sqp, *x1, *x2, *xc, *qp, *wc;
    unsigned* keys;
    int* idxp;
    cudaGetSymbolAddress((void**)&keys, g_keys);
    cudaGetSymbolAddress((void**)&sqp,  g_sq);
    cudaGetSymbolAddress((void**)&idxp, g_idx);
    cudaGetSymbolAddress((void**)&x1,   g_x1);
    cudaGetSymbolAddress((void**)&x2,   g_x2);
    cudaGetSymbolAddress((void**)&xc,   g_xc);
    cudaGetSymbolAddress((void**)&qp,   g_qp);
    cudaGetSymbolAddress((void**)&wc,   g_wc);

    float* wc3 = wc;            // 192*1024
    float* wc2 = wc + 196608;   // 64*256
    float* wc1 = wc + 212992;   // 3*128

    static cudaStream_t s1 = nullptr;
    static cudaEvent_t ev[8];
    if (!s1) {
        cudaFuncSetAttribute(gather_kernel,
                             cudaFuncAttributeMaxDynamicSharedMemorySize, 65536);
        cudaStreamCreateWithFlags(&s1, cudaStreamNonBlocking);
        for (int i = 0; i < 8; i++) cudaEventCreateWithFlags(&ev[i], cudaEventDisableTiming);
    }
    const int GSM = 65536;   // 2048 * 8 * 4 bytes

    dim3 symgrid(NPAIR, BB);

    // fork: side stream handles weight prep + feature GEMM chain
    cudaEventRecord(ev[0], 0);
    cudaStreamWaitEvent(s1, ev[0], 0);

    prepw_kernel<<<(3 * 64 + 255) / 256, 256, 0, s1>>>(W1, wc1, 3, 64);
    prepw_kernel<<<(64 * 128 + 255) / 256, 256, 0, s1>>>(W2, wc2, 64, 128);
    prepw_kernel<<<(192 * 512 + 255) / 256, 256, 0, s1>>>(W3, wc3, 192, 512);
    gemm_kernel<<<dim3(1, NPTS / 128), 256, 0, s1>>>(x, wc1, qp, 3, 128);
    cudaEventRecord(ev[1], s1);

    // ---- stage 1 selection chain (default stream)
    sq_kernel<<<(NPTS + 255) / 256, 256>>>(x, sqp, 3);
    d2sym_kernel<<<symgrid, 256>>>(x, sqp, keys, 3);
    knn_kernel<<<NPTS, 256>>>(keys, idxp);
    cudaStreamWaitEvent(0, ev[1], 0);
    gather_kernel<<<dim3(8, BB), 256, GSM>>>(qp, idxp, b1, x1, 64, 1);
    cudaEventRecord(ev[2], 0);                 // x1 ready, qp free

    // side: gemm2 (reads x1, writes qp)
    cudaStreamWaitEvent(s1, ev[2], 0);
    gemm_kernel<<<dim3(2, NPTS / 128), 256, 0, s1>>>(x1, wc2, qp, 64, 256);
    cudaEventRecord(ev[3], s1);

    // ---- stage 2 selection chain
    sq_kernel<<<(NPTS + 255) / 256, 256>>>(x1, sqp, 64);
    d2sym_kernel<<<symgrid, 256>>>(x1, sqp, keys, 64);
    knn_kernel<<<NPTS, 256>>>(keys, idxp);
    cudaStreamWaitEvent(0, ev[3], 0);
    gather_kernel<<<dim3(16, BB), 256, GSM>>>(qp, idxp, b2, x2, 128, 1);
    cudaEventRecord(ev[4], 0);                 // x2 ready, qp free

    // side: concat + gemm3
    cudaStreamWaitEvent(s1, ev[4], 0);
    concat_kernel<<<(NPTS * 48 + 255) / 256, 256, 0, s1>>>(x1, x2, xc);
    gemm_kernel<<<dim3(8, NPTS / 128), 256, 0, s1>>>(xc, wc3, qp, 192, 1024);
    cudaEventRecord(ev[5], s1);

    // ---- stage 3 selection chain
    sq_kernel<<<(NPTS + 255) / 256, 256>>>(x2, sqp, 128);
    d2sym_kernel<<<symgrid, 256>>>(x2, sqp, keys, 128);
    knn_kernel<<<NPTS, 256>>>(keys, idxp);
    cudaStreamWaitEvent(0, ev[5], 0);
    gather_kernel<<<dim3(64, BB), 256, GSM>>>(qp, idxp, b3, out, 512, 0);
}

// round 16
// speedup vs baseline: 1.3077x; 1.3077x over previous
#include <cuda_runtime.h>
#include <cfloat>

#define BB 8
#define NN 2048
#define KNBR 32
#define NPTS (BB*NN)
#define NBLK (NN/128)           // 16 tiles per dim
#define NPAIR (NBLK*(NBLK+1)/2) // 136 upper-tri block pairs
#define CHB 2                   // batches per pipeline chunk
#define NCHUNK (BB/CHB)         // 4 chunks

typedef unsigned long long u64;

__device__ __forceinline__ u64 pack2(float lo, float hi) {
    u64 r;
    asm("mov.b64 %0, {%1, %2};" : "=l"(r) : "f"(lo), "f"(hi));
    return r;
}
__device__ __forceinline__ float2 unpack2(u64 v) {
    float2 f;
    asm("mov.b64 {%0, %1}, %2;" : "=f"(f.x), "=f"(f.y) : "l"(v));
    return f;
}
__device__ __forceinline__ void fma2(u64& d, u64 a, u64 b) {
    asm("fma.rn.f32x2 %0, %1, %2, %0;" : "+l"(d) : "l"(a), "l"(b));
}
__device__ __forceinline__ unsigned flipkey(float f) {
    unsigned b = __float_as_uint(f);
    return (b & 0x80000000u) ? ~b : (b | 0x80000000u);
}

// ---------------- scratch (static device globals; no runtime alloc) ----------
__device__ unsigned g_keys[(size_t)NPTS * NN]; // pairwise keys (chunks stay L2-resident)
__device__ float g_sq[NPTS];
__device__ int   g_idx[NPTS * KNBR];
__device__ float g_x1[NPTS * 64];
__device__ float g_x2[NPTS * 128];
__device__ float g_xc[NPTS * 192];
__device__ float g_qp[(size_t)NPTS * 1024];  // [q | p] per point, max 2*512
__device__ float g_wc[256 * 1024];           // 3 disjoint combined-weight slices

// ---------------- squared norms ----------------------------------------------
__global__ void sq_kernel(const float* __restrict__ X, float* __restrict__ sq, int C) {
    int i = blockIdx.x * blockDim.x + threadIdx.x;
    if (i < NPTS) {
        const float* r = X + (size_t)i * C;
        float s = 0.f;
        for (int c = 0; c < C; c++) s += r[c] * r[c];
        sq[i] = s;
    }
}

// ---------------- pairwise d2 keys, symmetric, FFMA2, per-chunk ---------------
// grid (NPAIR, CHB); batch = b0 + blockIdx.y. Key stores are default (write-back)
// so the chunk stays L2-resident for the immediately following knn.
__global__ void __launch_bounds__(256, 2)
d2sym_kernel(const float* __restrict__ X, const float* __restrict__ sq,
             unsigned* __restrict__ keys, int C, int b0) {
    __shared__ __align__(16) float As[16][132];
    __shared__ __align__(16) float Bs[16][132];
    int b = b0 + blockIdx.y;
    int rem = blockIdx.x, bi = 0;
    while (rem >= NBLK - bi) { rem -= NBLK - bi; bi++; }
    int bj = bi + rem;
    int row0 = bi * 128, col0 = bj * 128;

    const float* Xb = X + (size_t)b * NN * C;
    int tid = threadIdx.x;
    int ty = tid >> 4, tx = tid & 15;
    u64 acc2[8][4];
#pragma unroll
    for (int i = 0; i < 8; i++)
#pragma unroll
        for (int j = 0; j < 4; j++) acc2[i][j] = 0ull;

    int kk = tid & 15, i0 = tid >> 4;

    if (C <= 16) {
        bool kin = (kk < C);
#pragma unroll
        for (int u = 0; u < 8; u++) {
            int i = i0 + (u << 4);
            As[kk][i] = kin ? Xb[(size_t)(row0 + i) * C + kk] : 0.f;
            Bs[kk][i] = kin ? Xb[(size_t)(col0 + i) * C + kk] : 0.f;
        }
        __syncthreads();
        for (int t = 0; t < C; t++) {
            float a[8], bv[8];
            *(float4*)&a[0]  = *(const float4*)&As[t][ty << 2];
            *(float4*)&a[4]  = *(const float4*)&As[t][64 + (ty << 2)];
            *(float4*)&bv[0] = *(const float4*)&Bs[t][tx << 2];
            *(float4*)&bv[4] = *(const float4*)&Bs[t][64 + (tx << 2)];
            u64 b2[4];
#pragma unroll
            for (int j = 0; j < 4; j++) b2[j] = pack2(bv[2 * j], bv[2 * j + 1]);
#pragma unroll
            for (int i = 0; i < 8; i++) {
                u64 a2 = pack2(a[i], a[i]);
#pragma unroll
                for (int j = 0; j < 4; j++) fma2(acc2[i][j], a2, b2[j]);
            }
        }
        __syncthreads();
    } else {
        for (int k0 = 0; k0 < C; k0 += 16) {
            int k = k0 + kk;
#pragma unroll
            for (int u = 0; u < 8; u++) {
                int i = i0 + (u << 4);
                As[kk][i] = Xb[(size_t)(row0 + i) * C + k];
                Bs[kk][i] = Xb[(size_t)(col0 + i) * C + k];
            }
            __syncthreads();
#pragma unroll
            for (int t = 0; t < 16; t++) {
                float a[8], bv[8];
                *(float4*)&a[0]  = *(const float4*)&As[t][ty << 2];
                *(float4*)&a[4]  = *(const float4*)&As[t][64 + (ty << 2)];
                *(float4*)&bv[0] = *(const float4*)&Bs[t][tx << 2];
                *(float4*)&bv[4] = *(const float4*)&Bs[t][64 + (tx << 2)];
                u64 b2[4];
#pragma unroll
                for (int j = 0; j < 4; j++) b2[j] = pack2(bv[2 * j], bv[2 * j + 1]);
#pragma unroll
                for (int i = 0; i < 8; i++) {
                    u64 a2 = pack2(a[i], a[i]);
#pragma unroll
                    for (int j = 0; j < 4; j++) fma2(acc2[i][j], a2, b2[j]);
                }
            }
            __syncthreads();
        }
    }

    unsigned kv[8][8];
#pragma unroll
    for (int i = 0; i < 8; i++) {
        int r = row0 + ((i < 4) ? ((ty << 2) + i) : (64 + (ty << 2) + i - 4));
        float sqr = sq[b * NN + r];
#pragma unroll
        for (int j = 0; j < 4; j++) {
            float2 f = unpack2(acc2[i][j]);
            int c0 = col0 + ((2*j < 4) ? ((tx << 2) + 2*j) : (64 + (tx << 2) + 2*j - 4));
            int c1 = col0 + ((2*j+1 < 4) ? ((tx << 2) + 2*j+1) : (64 + (tx << 2) + 2*j+1 - 4));
            float v0 = sqr + sq[b * NN + c0] - 2.f * f.x;
            float v1 = sqr + sq[b * NN + c1] - 2.f * f.y;
            if (r == c0) v0 = FLT_MAX;
            if (r == c1) v1 = FLT_MAX;
            kv[i][2*j]   = flipkey(v0);
            kv[i][2*j+1] = flipkey(v1);
        }
    }

    unsigned* kb = keys + (size_t)b * NN * NN;
#pragma unroll
    for (int i = 0; i < 8; i++) {
        int r = row0 + ((i < 4) ? ((ty << 2) + i) : (64 + (ty << 2) + i - 4));
        uint4 v0 = make_uint4(kv[i][0], kv[i][1], kv[i][2], kv[i][3]);
        uint4 v1 = make_uint4(kv[i][4], kv[i][5], kv[i][6], kv[i][7]);
        *(uint4*)&kb[(size_t)r * NN + col0 + (tx << 2)]      = v0;
        *(uint4*)&kb[(size_t)r * NN + col0 + 64 + (tx << 2)] = v1;
    }
    if (bi != bj) {
#pragma unroll
        for (int j = 0; j < 8; j++) {
            int c = col0 + ((j < 4) ? ((tx << 2) + j) : (64 + (tx << 2) + j - 4));
            uint4 lo = make_uint4(kv[0][j], kv[1][j], kv[2][j], kv[3][j]);
            uint4 hi = make_uint4(kv[4][j], kv[5][j], kv[6][j], kv[7][j]);
            *(uint4*)&kb[(size_t)c * NN + row0 + (ty << 2)]      = lo;
            *(uint4*)&kb[(size_t)c * NN + row0 + 64 + (ty << 2)] = hi;
        }
    }
}

// ---------------- top-K via 4-pass (8-bit) radix select, per-chunk -------------
__global__ void __launch_bounds__(256)
knn_kernel(const unsigned* __restrict__ keys_g, int* __restrict__ idxout, int p0) {
    __shared__ int hist[2048];      // 256 used as bins; full 2048 reused as tie buffer
    __shared__ int wsum[8], wsumex[8];
    __shared__ int ctrlB, ctrlBelow;
    __shared__ int cnt, eqcnt;

    int p = p0 + blockIdx.x;
    int t = threadIdx.x, lane = t & 31, wid = t >> 5;

    const uint4* row4 = (const uint4*)(keys_g + (size_t)p * NN);
    unsigned key[8];
#pragma unroll
    for (int u = 0; u < 2; u++) {
        uint4 f = __ldcs(&row4[t + (u << 8)]);
        key[u * 4 + 0] = f.x; key[u * 4 + 1] = f.y;
        key[u * 4 + 2] = f.z; key[u * 4 + 3] = f.w;
    }

    unsigned pval = 0, pmask = 0;
    int base = 0;
#pragma unroll
    for (int pass = 0; pass < 4; pass++) {
        const int shift = 24 - (pass << 3);
        hist[t] = 0;
        __syncthreads();
        if (pass == 0) {
#pragma unroll
            for (int e = 0; e < 8; e++) {
                int bin = key[e] >> 24;
                unsigned peers = __match_any_sync(0xffffffffu, bin);
                int leader = __ffs(peers) - 1;
                if (lane == leader) atomicAdd(&hist[bin], __popc(peers));
            }
        } else {
#pragma unroll
            for (int e = 0; e < 8; e++) {
                unsigned k = key[e];
                if ((k & pmask) == pval) atomicAdd(&hist[(k >> shift) & 255], 1);
            }
        }
        __syncthreads();
        int s = hist[t];
        int incl = s;
#pragma unroll
        for (int off = 1; off < 32; off <<= 1) {
            int n = __shfl_up_sync(0xffffffffu, incl, off);
            if (lane >= off) incl += n;
        }
        if (lane == 31) wsum[wid] = incl;
        __syncthreads();
        if (t == 0) {
            int run = 0;
            for (int w = 0; w < 8; w++) { wsumex[w] = run; run += wsum[w]; }
        }
        __syncthreads();
        int excl = wsumex[wid] + incl - s;
        int need = KNBR - base;
        if (excl < need && need <= excl + s) {
            ctrlB = t; ctrlBelow = excl;
        }
        __syncthreads();
        base += ctrlBelow;
        pval |= ((unsigned)ctrlB) << shift;
        pmask |= 255u << shift;
        __syncthreads();
    }

    const unsigned T = pval;
    if (t == 0) { cnt = 0; eqcnt = 0; }
    __syncthreads();
#pragma unroll
    for (int e = 0; e < 8; e++) {
        unsigned k = key[e];
        int i = (t << 2) + ((e >> 2) << 10) + (e & 3);
        if (k < T) {
            int pos = atomicAdd(&cnt, 1);
            idxout[p * KNBR + pos] = i;
        } else if (k == T) {
            int q = atomicAdd(&eqcnt, 1);
            hist[q] = i;
        }
    }
    __syncthreads();
    int c = cnt, E = eqcnt, tn = KNBR - c;
    if (E == tn) {
        for (int j = t; j < E; j += 256) idxout[p * KNBR + c + j] = hist[j];
    } else {
        for (int j = t; j < E; j += 256) {
            int mi = hist[j], r = 0;
            for (int q = 0; q < E; q++) r += (hist[q] < mi);
            if (r < tn) idxout[p * KNBR + c + r] = mi;
        }
    }
}

// ---------------- combined weight prep: wc = [Wb | Wa - Wb] -------------------
__global__ void prepw_kernel(const float* __restrict__ W, float* __restrict__ wc,
                             int C, int Cout) {
    int i = blockIdx.x * blockDim.x + threadIdx.x;
    if (i < C * Cout) {
        int c = i / Cout, d = i % Cout;
        float wa = W[c * Cout + d];
        float wb = W[(C + c) * Cout + d];
        wc[c * (2 * Cout) + d] = wb;
        wc[c * (2 * Cout) + Cout + d] = wa - wb;
    }
}

// ---------------- generic GEMM with FFMA2 inner loop ---------------------------
__global__ void __launch_bounds__(256, 2)
gemm_kernel(const float* __restrict__ A, const float* __restrict__ Bm,
            float* __restrict__ Cm, int Kd, int Nd) {
    __shared__ __align__(16) float As[16][132];
    __shared__ __align__(16) float Bs[16][132];
    int row0 = blockIdx.y * 128, col0 = blockIdx.x * 128;
    int tid = threadIdx.x;
    int ty = tid >> 4, tx = tid & 15;
    u64 acc2[8][4];
#pragma unroll
    for (int i = 0; i < 8; i++)
#pragma unroll
        for (int j = 0; j < 4; j++) acc2[i][j] = 0ull;

    int kk = tid & 15, i0 = tid >> 4;
    int j0 = tid & 127, kb = tid >> 7;

    for (int k0 = 0; k0 < Kd; k0 += 16) {
        int k = k0 + kk;
        bool kin = (k < Kd);
#pragma unroll
        for (int u = 0; u < 8; u++) {
            int i = i0 + (u << 4);
            As[kk][i] = kin ? A[(size_t)(row0 + i) * Kd + k] : 0.f;
        }
#pragma unroll
        for (int u = 0; u < 8; u++) {
            int kr = kb + (u << 1);
            int kg = k0 + kr;
            Bs[kr][j0] = (kg < Kd) ? Bm[(size_t)kg * Nd + col0 + j0] : 0.f;
        }
        __syncthreads();
#pragma unroll
        for (int t = 0; t < 16; t++) {
            float a[8], bv[8];
            *(float4*)&a[0]  = *(const float4*)&As[t][ty << 2];
            *(float4*)&a[4]  = *(const float4*)&As[t][64 + (ty << 2)];
            *(float4*)&bv[0] = *(const float4*)&Bs[t][tx << 2];
            *(float4*)&bv[4] = *(const float4*)&Bs[t][64 + (tx << 2)];
            u64 b2[4];
#pragma unroll
            for (int j = 0; j < 4; j++) b2[j] = pack2(bv[2 * j], bv[2 * j + 1]);
#pragma unroll
            for (int i = 0; i < 8; i++) {
                u64 a2 = pack2(a[i], a[i]);
#pragma unroll
                for (int j = 0; j < 4; j++) fma2(acc2[i][j], a2, b2[j]);
            }
        }
        __syncthreads();
    }
#pragma unroll
    for (int i = 0; i < 8; i++) {
        int r = row0 + ((i < 4) ? ((ty << 2) + i) : (64 + (ty << 2) + i - 4));
        float2 f0 = unpack2(acc2[i][0]), f1 = unpack2(acc2[i][1]);
        float2 f2 = unpack2(acc2[i][2]), f3 = unpack2(acc2[i][3]);
        float4 v0 = make_float4(f0.x, f0.y, f1.x, f1.y);
        float4 v1 = make_float4(f2.x, f2.y, f3.x, f3.y);
        *(float4*)&Cm[(size_t)r * Nd + col0 + (tx << 2)]      = v0;
        *(float4*)&Cm[(size_t)r * Nd + col0 + 64 + (tx << 2)] = v1;
    }
}

// ---------------- gather-max + bias + activation (coalesced, multi-point) -----
__global__ void __launch_bounds__(128)
gather_kernel(const float* __restrict__ qp, const int* __restrict__ idx,
              const float* __restrict__ bias, float* __restrict__ out,
              int Cout, int relu) {
    __shared__ int nbr[8][KNBR];
    int c4 = Cout >> 2;
    int ppb = 128 / c4;
    int lp = threadIdx.x / c4, d = threadIdx.x - lp * c4;
    int p0 = blockIdx.x * ppb;
    int p = p0 + lp;
    int b = p / NN;
    int ld4 = c4 << 1;
    const float4* qp4 = (const float4*)qp;
    size_t baserow = (size_t)b * NN;

    for (int i = threadIdx.x; i < ppb * KNBR; i += 128)
        nbr[i / KNBR][i % KNBR] = idx[(size_t)p0 * KNBR + i];
    __syncthreads();

    float4 m = make_float4(-FLT_MAX, -FLT_MAX, -FLT_MAX, -FLT_MAX);
#pragma unroll 8
    for (int j = 0; j < KNBR; j++) {
        float4 v = qp4[(baserow + nbr[lp][j]) * ld4 + d];
        m.x = fmaxf(m.x, v.x); m.y = fmaxf(m.y, v.y);
        m.z = fmaxf(m.z, v.z); m.w = fmaxf(m.w, v.w);
    }
    float4 pp = qp4[(size_t)p * ld4 + c4 + d];
    float4 bb = ((const float4*)bias)[d];
    float4 r;
    r.x = pp.x + bb.x + m.x; r.y = pp.y + bb.y + m.y;
    r.z = pp.z + bb.z + m.z; r.w = pp.w + bb.w + m.w;
    if (relu) {
        r.x = fmaxf(r.x, 0.f); r.y = fmaxf(r.y, 0.f);
        r.z = fmaxf(r.z, 0.f); r.w = fmaxf(r.w, 0.f);
    }
    ((float4*)out)[(size_t)p * c4 + d] = r;
}

// ---------------- concat x1 | x2 (float4) --------------------------------------
__global__ void concat_kernel(const float* __restrict__ x1, const float* __restrict__ x2,
                              float* __restrict__ xc) {
    int i = blockIdx.x * blockDim.x + threadIdx.x;
    if (i < NPTS * 48) {
        int p = i / 48, c = i % 48;
        float4 v = (c < 16) ? ((const float4*)x1)[p * 16 + c]
                            : ((const float4*)x2)[p * 32 + (c - 16)];
        ((float4*)xc)[i] = v;
    }
}

// ---------------- launch: chunked d2sym/knn pipeline + gemm side stream --------
extern "C" void kernel_launch(void* const* d_in, const int* in_sizes, int n_in,
                              void* d_out, int out_size) {
    const float* x  = (const float*)d_in[0];
    const float* W1 = (const float*)d_in[1];
    const float* b1 = (const float*)d_in[2];
    const float* W2 = (const float*)d_in[3];
    const float* b2 = (const float*)d_in[4];
    const float* W3 = (const float*)d_in[5];
    const float* b3 = (const float*)d_in[6];
    float* out = (float*)d_out;

    float *sqp, *x1, *x2, *xc, *qp, *wc;
    unsigned* keys;
    int* idxp;
    cudaGetSymbolAddress((void**)&keys, g_keys);
    cudaGetSymbolAddress((void**)&sqp,  g_sq);
    cudaGetSymbolAddress((void**)&idxp, g_idx);
    cudaGetSymbolAddress((void**)&x1,   g_x1);
    cudaGetSymbolAddress((void**)&x2,   g_x2);
    cudaGetSymbolAddress((void**)&xc,   g_xc);
    cudaGetSymbolAddress((void**)&qp,   g_qp);
    cudaGetSymbolAddress((void**)&wc,   g_wc);

    float* wc3 = wc;            // 192*1024
    float* wc2 = wc + 196608;   // 64*256
    float* wc1 = wc + 212992;   // 3*128

    static cudaStream_t s1 = nullptr, s2 = nullptr;
    static cudaEvent_t evt[32];
    if (!s1) {
        cudaStreamCreateWithFlags(&s1, cudaStreamNonBlocking);
        cudaStreamCreateWithFlags(&s2, cudaStreamNonBlocking);
        for (int i = 0; i < 32; i++) cudaEventCreateWithFlags(&evt[i], cudaEventDisableTiming);
    }
    int ne = 0;

    dim3 cgrid(NPAIR, CHB);

    // fork side streams
    cudaEvent_t evF = evt[ne++];
    cudaEventRecord(evF, 0);
    cudaStreamWaitEvent(s1, evF, 0);
    cudaStreamWaitEvent(s2, evF, 0);

    // s1: weight prep + gemm1
    prepw_kernel<<<(3 * 64 + 255) / 256, 256, 0, s1>>>(W1, wc1, 3, 64);
    prepw_kernel<<<(64 * 128 + 255) / 256, 256, 0, s1>>>(W2, wc2, 64, 128);
    prepw_kernel<<<(192 * 512 + 255) / 256, 256, 0, s1>>>(W3, wc3, 192, 512);
    gemm_kernel<<<dim3(1, NPTS / 128), 256, 0, s1>>>(x, wc1, qp, 3, 128);
    cudaEvent_t evGemm = evt[ne++];
    cudaEventRecord(evGemm, s1);

    const float* xs[3] = { x, x1, x2 };
    const int    Cs[3] = { 3, 64, 128 };

    for (int st = 0; st < 3; st++) {
        const float* xin = xs[st];
        int C = Cs[st];

        // s0: sq + chunked d2sym (each chunk's keys stay L2-resident)
        sq_kernel<<<(NPTS + 255) / 256, 256>>>(xin, sqp, C);
        cudaEvent_t evD[NCHUNK];
        for (int c = 0; c < NCHUNK; c++) {
            d2sym_kernel<<<cgrid, 256>>>(xin, sqp, keys, C, c * CHB);
            evD[c] = evt[ne++];
            cudaEventRecord(evD[c], 0);
        }
        // s2: chunked knn, overlapping next d2sym chunk
        for (int c = 0; c < NCHUNK; c++) {
            cudaStreamWaitEvent(s2, evD[c], 0);
            knn_kernel<<<CHB * NN, 256, 0, s2>>>(keys, idxp, c * CHB * NN);
        }
        // s2: gather after all knn chunks + this stage's gemm
        cudaStreamWaitEvent(s2, evGemm, 0);
        if (st == 0)
            gather_kernel<<<NPTS / 8, 128, 0, s2>>>(qp, idxp, b1, x1, 64, 1);
        else if (st == 1)
            gather_kernel<<<NPTS / 4, 128, 0, s2>>>(qp, idxp, b2, x2, 128, 1);
        else
            gather_kernel<<<NPTS, 128, 0, s2>>>(qp, idxp, b3, out, 512, 0);
        cudaEvent_t evG = evt[ne++];
        cudaEventRecord(evG, s2);

        // gate next stage: s0 (sq/d2sym read x_{st+1}, write keys) and s1 (gemm)
        cudaStreamWaitEvent(0, evG, 0);
        if (st == 0) {
            cudaStreamWaitEvent(s1, evG, 0);
            gemm_kernel<<<dim3(2, NPTS / 128), 256, 0, s1>>>(x1, wc2, qp, 64, 256);
            evGemm = evt[ne++];
            cudaEventRecord(evGemm, s1);
        } else if (st == 1) {
            cudaStreamWaitEvent(s1, evG, 0);
            concat_kernel<<<(NPTS * 48 + 255) / 256, 256, 0, s1>>>(x1, x2, xc);
            gemm_kernel<<<dim3(8, NPTS / 128), 256, 0, s1>>>(xc, wc3, qp, 192, 1024);
            evGemm = evt[ne++];
            cudaEventRecord(evGemm, s1);
        }
    }
}

// round 17
// speedup vs baseline: 1.4539x; 1.1118x over previous
#include <cuda_runtime.h>
#include <cfloat>

#define BB 8
#define NN 2048
#define KNBR 32
#define NPTS (BB*NN)
#define NBLK (NN/128)           // 16 tiles per dim
#define NPAIR (NBLK*(NBLK+1)/2) // 136 upper-tri block pairs

typedef unsigned long long u64;
typedef unsigned short u16;

__device__ __forceinline__ u64 pack2(float lo, float hi) {
    u64 r;
    asm("mov.b64 %0, {%1, %2};" : "=l"(r) : "f"(lo), "f"(hi));
    return r;
}
__device__ __forceinline__ float2 unpack2(u64 v) {
    float2 f;
    asm("mov.b64 {%0, %1}, %2;" : "=f"(f.x), "=f"(f.y) : "l"(v));
    return f;
}
__device__ __forceinline__ void fma2(u64& d, u64 a, u64 b) {
    asm("fma.rn.f32x2 %0, %1, %2, %0;" : "+l"(d) : "l"(a), "l"(b));
}
__device__ __forceinline__ unsigned flipkey(float f) {
    unsigned b = __float_as_uint(f);
    return (b & 0x80000000u) ? ~b : (b | 0x80000000u);
}

// ---------------- scratch (static device globals; no runtime alloc) ----------
__device__ u16   g_keys[(size_t)NPTS * NN];  // 67MB: top-16-bit monotone keys
__device__ float g_sq[NPTS];
__device__ int   g_idx[NPTS * KNBR];
__device__ float g_x1[NPTS * 64];
__device__ float g_x2[NPTS * 128];
__device__ float g_xc[NPTS * 192];
__device__ float g_qp[(size_t)NPTS * 1024];  // [q | p] per point, max 2*512
__device__ float g_wc[256 * 1024];           // 3 disjoint combined-weight slices

// ---------------- squared norms ----------------------------------------------
__global__ void sq_kernel(const float* __restrict__ X, float* __restrict__ sq, int C) {
    int i = blockIdx.x * blockDim.x + threadIdx.x;
    if (i < NPTS) {
        const float* r = X + (size_t)i * C;
        float s = 0.f;
        for (int c = 0; c < C; c++) s += r[c] * r[c];
        sq[i] = s;
    }
}

// ---------------- pairwise d2 16-bit keys, symmetric, FFMA2 -------------------
__global__ void __launch_bounds__(256, 2)
d2sym_kernel(const float* __restrict__ X, const float* __restrict__ sq,
             u16* __restrict__ keys, int C) {
    __shared__ __align__(16) float As[16][132];
    __shared__ __align__(16) float Bs[16][132];
    int b = blockIdx.y;
    int rem = blockIdx.x, bi = 0;
    while (rem >= NBLK - bi) { rem -= NBLK - bi; bi++; }
    int bj = bi + rem;
    int row0 = bi * 128, col0 = bj * 128;

    const float* Xb = X + (size_t)b * NN * C;
    int tid = threadIdx.x;
    int ty = tid >> 4, tx = tid & 15;
    u64 acc2[8][4];
#pragma unroll
    for (int i = 0; i < 8; i++)
#pragma unroll
        for (int j = 0; j < 4; j++) acc2[i][j] = 0ull;

    int kk = tid & 15, i0 = tid >> 4;

    if (C <= 16) {
        bool kin = (kk < C);
#pragma unroll
        for (int u = 0; u < 8; u++) {
            int i = i0 + (u << 4);
            As[kk][i] = kin ? Xb[(size_t)(row0 + i) * C + kk] : 0.f;
            Bs[kk][i] = kin ? Xb[(size_t)(col0 + i) * C + kk] : 0.f;
        }
        __syncthreads();
        for (int t = 0; t < C; t++) {
            float a[8], bv[8];
            *(float4*)&a[0]  = *(const float4*)&As[t][ty << 2];
            *(float4*)&a[4]  = *(const float4*)&As[t][64 + (ty << 2)];
            *(float4*)&bv[0] = *(const float4*)&Bs[t][tx << 2];
            *(float4*)&bv[4] = *(const float4*)&Bs[t][64 + (tx << 2)];
            u64 b2[4];
#pragma unroll
            for (int j = 0; j < 4; j++) b2[j] = pack2(bv[2 * j], bv[2 * j + 1]);
#pragma unroll
            for (int i = 0; i < 8; i++) {
                u64 a2 = pack2(a[i], a[i]);
#pragma unroll
                for (int j = 0; j < 4; j++) fma2(acc2[i][j], a2, b2[j]);
            }
        }
        __syncthreads();
    } else {
        for (int k0 = 0; k0 < C; k0 += 16) {
            int k = k0 + kk;
#pragma unroll
            for (int u = 0; u < 8; u++) {
                int i = i0 + (u << 4);
                As[kk][i] = Xb[(size_t)(row0 + i) * C + k];
                Bs[kk][i] = Xb[(size_t)(col0 + i) * C + k];
            }
            __syncthreads();
#pragma unroll
            for (int t = 0; t < 16; t++) {
                float a[8], bv[8];
                *(float4*)&a[0]  = *(const float4*)&As[t][ty << 2];
                *(float4*)&a[4]  = *(const float4*)&As[t][64 + (ty << 2)];
                *(float4*)&bv[0] = *(const float4*)&Bs[t][tx << 2];
                *(float4*)&bv[4] = *(const float4*)&Bs[t][64 + (tx << 2)];
                u64 b2[4];
#pragma unroll
                for (int j = 0; j < 4; j++) b2[j] = pack2(bv[2 * j], bv[2 * j + 1]);
#pragma unroll
                for (int i = 0; i < 8; i++) {
                    u64 a2 = pack2(a[i], a[i]);
#pragma unroll
                    for (int j = 0; j < 4; j++) fma2(acc2[i][j], a2, b2[j]);
                }
            }
            __syncthreads();
        }
    }

    u16 kv[8][8];
#pragma unroll
    for (int i = 0; i < 8; i++) {
        int r = row0 + ((i < 4) ? ((ty << 2) + i) : (64 + (ty << 2) + i - 4));
        float sqr = sq[b * NN + r];
#pragma unroll
        for (int j = 0; j < 4; j++) {
            float2 f = unpack2(acc2[i][j]);
            int c0 = col0 + ((2*j < 4) ? ((tx << 2) + 2*j) : (64 + (tx << 2) + 2*j - 4));
            int c1 = col0 + ((2*j+1 < 4) ? ((tx << 2) + 2*j+1) : (64 + (tx << 2) + 2*j+1 - 4));
            float v0 = sqr + sq[b * NN + c0] - 2.f * f.x;
            float v1 = sqr + sq[b * NN + c1] - 2.f * f.y;
            if (r == c0) v0 = FLT_MAX;
            if (r == c1) v1 = FLT_MAX;
            kv[i][2*j]   = (u16)(flipkey(v0) >> 16);
            kv[i][2*j+1] = (u16)(flipkey(v1) >> 16);
        }
    }

    u16* kb = keys + (size_t)b * NN * NN;
#pragma unroll
    for (int i = 0; i < 8; i++) {
        int r = row0 + ((i < 4) ? ((ty << 2) + i) : (64 + (ty << 2) + i - 4));
        ushort4 v0 = make_ushort4(kv[i][0], kv[i][1], kv[i][2], kv[i][3]);
        ushort4 v1 = make_ushort4(kv[i][4], kv[i][5], kv[i][6], kv[i][7]);
        *(ushort4*)&kb[(size_t)r * NN + col0 + (tx << 2)]      = v0;
        *(ushort4*)&kb[(size_t)r * NN + col0 + 64 + (tx << 2)] = v1;
    }
    if (bi != bj) {
#pragma unroll
        for (int j = 0; j < 8; j++) {
            int c = col0 + ((j < 4) ? ((tx << 2) + j) : (64 + (tx << 2) + j - 4));
            ushort4 lo = make_ushort4(kv[0][j], kv[1][j], kv[2][j], kv[3][j]);
            ushort4 hi = make_ushort4(kv[4][j], kv[5][j], kv[6][j], kv[7][j]);
            *(ushort4*)&kb[(size_t)c * NN + row0 + (ty << 2)]      = lo;
            *(ushort4*)&kb[(size_t)c * NN + row0 + 64 + (ty << 2)] = hi;
        }
    }
}

// ---------------- top-K: 2-pass 16-bit radix select + exact refinement ---------
// Select by 16-bit key prefix; candidates tied at the threshold prefix are
// refined by recomputing exact d2 (so the chosen set matches full-precision
// selection up to sub-2^-24 rounding) with lowest-index tie-break.
__global__ void __launch_bounds__(256)
knn_kernel(const u16* __restrict__ keys16, int* __restrict__ idxout,
           const float* __restrict__ X, const float* __restrict__ sqn, int C) {
    __shared__ int tiebuf[2048];
    __shared__ unsigned fkey[2048];
    __shared__ float xq[128];
    __shared__ int hist[256];
    __shared__ int wsum[8], wsumex[8];
    __shared__ int ctrlB, ctrlBelow;
    __shared__ int cnt, eqcnt;

    int p = blockIdx.x;
    int t = threadIdx.x, lane = t & 31, wid = t >> 5;

    const uint4* row4 = (const uint4*)(keys16 + (size_t)p * NN);
    uint4 f = __ldcs(&row4[t]);          // 8 u16 keys; index of key[e] = t*8+e
    unsigned key[8];
    key[0] = f.x & 0xffffu; key[1] = f.x >> 16;
    key[2] = f.y & 0xffffu; key[3] = f.y >> 16;
    key[4] = f.z & 0xffffu; key[5] = f.z >> 16;
    key[6] = f.w & 0xffffu; key[7] = f.w >> 16;

    unsigned pval = 0, pmask = 0;
    int base = 0;
    if (t == 0) { cnt = 0; eqcnt = 0; }
#pragma unroll
    for (int pass = 0; pass < 2; pass++) {
        const int shift = 8 - (pass << 3);
        hist[t] = 0;
        __syncthreads();
        if (pass == 0) {
#pragma unroll
            for (int e = 0; e < 8; e++) {
                int bin = key[e] >> 8;
                unsigned peers = __match_any_sync(0xffffffffu, bin);
                int leader = __ffs(peers) - 1;
                if (lane == leader) atomicAdd(&hist[bin], __popc(peers));
            }
        } else {
#pragma unroll
            for (int e = 0; e < 8; e++) {
                unsigned k = key[e];
                if ((k & pmask) == pval) atomicAdd(&hist[k & 255], 1);
            }
        }
        __syncthreads();
        int s = hist[t];
        int incl = s;
#pragma unroll
        for (int off = 1; off < 32; off <<= 1) {
            int n = __shfl_up_sync(0xffffffffu, incl, off);
            if (lane >= off) incl += n;
        }
        if (lane == 31) wsum[wid] = incl;
        __syncthreads();
        if (t == 0) {
            int run = 0;
            for (int w = 0; w < 8; w++) { wsumex[w] = run; run += wsum[w]; }
        }
        __syncthreads();
        int excl = wsumex[wid] + incl - s;
        int need = KNBR - base;
        if (excl < need && need <= excl + s) { ctrlB = t; ctrlBelow = excl; }
        __syncthreads();
        base += ctrlBelow;
        pval |= ((unsigned)ctrlB) << shift;
        pmask |= 255u << shift;
        __syncthreads();
    }

    const unsigned T = pval;     // 16-bit threshold prefix
#pragma unroll
    for (int e = 0; e < 8; e++) {
        unsigned k = key[e];
        int i = (t << 3) + e;
        if (k < T) {
            int pos = atomicAdd(&cnt, 1);
            idxout[p * KNBR + pos] = i;
        } else if (k == T) {
            int q = atomicAdd(&eqcnt, 1);
            tiebuf[q] = i;
        }
    }
    __syncthreads();
    int c = cnt, E = eqcnt, tn = KNBR - c;   // tn >= 1, E >= tn
    if (E == tn) {
        for (int j = t; j < E; j += 256) idxout[p * KNBR + c + j] = tiebuf[j];
        return;
    }
    // refinement: recompute exact d2 for the E in-bin candidates
    int bb = p / NN;
    size_t brow = (size_t)bb * NN;
    for (int c0 = t; c0 < C; c0 += 256) xq[c0] = X[((size_t)p) * C + c0];
    __syncthreads();
    float sp = sqn[p];
    for (int j = t; j < E; j += 256) {
        int i = tiebuf[j];
        const float* xr = X + (brow + i) * C;
        float dot = 0.f;
        for (int c0 = 0; c0 < C; c0++) dot += xq[c0] * xr[c0];
        float d = sp + sqn[brow + i] - 2.f * dot;
        fkey[j] = flipkey(d);
    }
    __syncthreads();
    for (int j = t; j < E; j += 256) {
        unsigned fk = fkey[j];
        int mi = tiebuf[j], r = 0;
        for (int q = 0; q < E; q++)
            r += (fkey[q] < fk) || (fkey[q] == fk && tiebuf[q] < mi);
        if (r < tn) idxout[p * KNBR + c + r] = mi;
    }
}

// ---------------- combined weight prep: wc = [Wb | Wa - Wb] -------------------
__global__ void prepw_kernel(const float* __restrict__ W, float* __restrict__ wc,
                             int C, int Cout) {
    int i = blockIdx.x * blockDim.x + threadIdx.x;
    if (i < C * Cout) {
        int c = i / Cout, d = i % Cout;
        float wa = W[c * Cout + d];
        float wb = W[(C + c) * Cout + d];
        wc[c * (2 * Cout) + d] = wb;
        wc[c * (2 * Cout) + Cout + d] = wa - wb;
    }
}

// ---------------- generic GEMM with FFMA2 inner loop ---------------------------
__global__ void __launch_bounds__(256, 2)
gemm_kernel(const float* __restrict__ A, const float* __restrict__ Bm,
            float* __restrict__ Cm, int Kd, int Nd) {
    __shared__ __align__(16) float As[16][132];
    __shared__ __align__(16) float Bs[16][132];
    int row0 = blockIdx.y * 128, col0 = blockIdx.x * 128;
    int tid = threadIdx.x;
    int ty = tid >> 4, tx = tid & 15;
    u64 acc2[8][4];
#pragma unroll
    for (int i = 0; i < 8; i++)
#pragma unroll
        for (int j = 0; j < 4; j++) acc2[i][j] = 0ull;

    int kk = tid & 15, i0 = tid >> 4;
    int j0 = tid & 127, kb = tid >> 7;

    for (int k0 = 0; k0 < Kd; k0 += 16) {
        int k = k0 + kk;
        bool kin = (k < Kd);
#pragma unroll
        for (int u = 0; u < 8; u++) {
            int i = i0 + (u << 4);
            As[kk][i] = kin ? A[(size_t)(row0 + i) * Kd + k] : 0.f;
        }
#pragma unroll
        for (int u = 0; u < 8; u++) {
            int kr = kb + (u << 1);
            int kg = k0 + kr;
            Bs[kr][j0] = (kg < Kd) ? Bm[(size_t)kg * Nd + col0 + j0] : 0.f;
        }
        __syncthreads();
#pragma unroll
        for (int t = 0; t < 16; t++) {
            float a[8], bv[8];
            *(float4*)&a[0]  = *(const float4*)&As[t][ty << 2];
            *(float4*)&a[4]  = *(const float4*)&As[t][64 + (ty << 2)];
            *(float4*)&bv[0] = *(const float4*)&Bs[t][tx << 2];
            *(float4*)&bv[4] = *(const float4*)&Bs[t][64 + (tx << 2)];
            u64 b2[4];
#pragma unroll
            for (int j = 0; j < 4; j++) b2[j] = pack2(bv[2 * j], bv[2 * j + 1]);
#pragma unroll
            for (int i = 0; i < 8; i++) {
                u64 a2 = pack2(a[i], a[i]);
#pragma unroll
                for (int j = 0; j < 4; j++) fma2(acc2[i][j], a2, b2[j]);
            }
        }
        __syncthreads();
    }
#pragma unroll
    for (int i = 0; i < 8; i++) {
        int r = row0 + ((i < 4) ? ((ty << 2) + i) : (64 + (ty << 2) + i - 4));
        float2 f0 = unpack2(acc2[i][0]), f1 = unpack2(acc2[i][1]);
        float2 f2 = unpack2(acc2[i][2]), f3 = unpack2(acc2[i][3]);
        float4 v0 = make_float4(f0.x, f0.y, f1.x, f1.y);
        float4 v1 = make_float4(f2.x, f2.y, f3.x, f3.y);
        *(float4*)&Cm[(size_t)r * Nd + col0 + (tx << 2)]      = v0;
        *(float4*)&Cm[(size_t)r * Nd + col0 + 64 + (tx << 2)] = v1;
    }
}

// ---------------- gather-max + bias + activation (coalesced, multi-point) -----
__global__ void __launch_bounds__(128)
gather_kernel(const float* __restrict__ qp, const int* __restrict__ idx,
              const float* __restrict__ bias, float* __restrict__ out,
              int Cout, int relu) {
    __shared__ int nbr[8][KNBR];
    int c4 = Cout >> 2;
    int ppb = 128 / c4;
    int lp = threadIdx.x / c4, d = threadIdx.x - lp * c4;
    int p0 = blockIdx.x * ppb;
    int p = p0 + lp;
    int b = p / NN;
    int ld4 = c4 << 1;
    const float4* qp4 = (const float4*)qp;
    size_t baserow = (size_t)b * NN;

    for (int i = threadIdx.x; i < ppb * KNBR; i += 128)
        nbr[i / KNBR][i % KNBR] = idx[(size_t)p0 * KNBR + i];
    __syncthreads();

    float4 m = make_float4(-FLT_MAX, -FLT_MAX, -FLT_MAX, -FLT_MAX);
#pragma unroll 8
    for (int j = 0; j < KNBR; j++) {
        float4 v = qp4[(baserow + nbr[lp][j]) * ld4 + d];
        m.x = fmaxf(m.x, v.x); m.y = fmaxf(m.y, v.y);
        m.z = fmaxf(m.z, v.z); m.w = fmaxf(m.w, v.w);
    }
    float4 pp = qp4[(size_t)p * ld4 + c4 + d];
    float4 bb = ((const float4*)bias)[d];
    float4 r;
    r.x = pp.x + bb.x + m.x; r.y = pp.y + bb.y + m.y;
    r.z = pp.z + bb.z + m.z; r.w = pp.w + bb.w + m.w;
    if (relu) {
        r.x = fmaxf(r.x, 0.f); r.y = fmaxf(r.y, 0.f);
        r.z = fmaxf(r.z, 0.f); r.w = fmaxf(r.w, 0.f);
    }
    ((float4*)out)[(size_t)p * c4 + d] = r;
}

// ---------------- concat x1 | x2 (float4) --------------------------------------
__global__ void concat_kernel(const float* __restrict__ x1, const float* __restrict__ x2,
                              float* __restrict__ xc) {
    int i = blockIdx.x * blockDim.x + threadIdx.x;
    if (i < NPTS * 48) {
        int p = i / 48, c = i % 48;
        float4 v = (c < 16) ? ((const float4*)x1)[p * 16 + c]
                            : ((const float4*)x2)[p * 32 + (c - 16)];
        ((float4*)xc)[i] = v;
    }
}

// ---------------- launch (round-9 two-stream schedule) -------------------------
extern "C" void kernel_launch(void* const* d_in, const int* in_sizes, int n_in,
                              void* d_out, int out_size) {
    const float* x  = (const float*)d_in[0];
    const float* W1 = (const float*)d_in[1];
    const float* b1 = (const float*)d_in[2];
    const float* W2 = (const float*)d_in[3];
    const float* b2 = (const float*)d_in[4];
    const float* W3 = (const float*)d_in[5];
    const float* b3 = (const float*)d_in[6];
    float* out = (float*)d_out;

    float *sqp, *x1, *x2, *xc, *qp, *wc;
    u16* keys;
    int* idxp;
    cudaGetSymbolAddress((void**)&keys, g_keys);
    cudaGetSymbolAddress((void**)&sqp,  g_sq);
    cudaGetSymbolAddress((void**)&idxp, g_idx);
    cudaGetSymbolAddress((void**)&x1,   g_x1);
    cudaGetSymbolAddress((void**)&x2,   g_x2);
    cudaGetSymbolAddress((void**)&xc,   g_xc);
    cudaGetSymbolAddress((void**)&qp,   g_qp);
    cudaGetSymbolAddress((void**)&wc,   g_wc);

    float* wc3 = wc;            // 192*1024
    float* wc2 = wc + 196608;   // 64*256
    float* wc1 = wc + 212992;   // 3*128

    static cudaStream_t s1 = nullptr;
    static cudaEvent_t ev[8];
    if (!s1) {
        cudaStreamCreateWithFlags(&s1, cudaStreamNonBlocking);
        for (int i = 0; i < 8; i++) cudaEventCreateWithFlags(&ev[i], cudaEventDisableTiming);
    }

    dim3 symgrid(NPAIR, BB);

    // fork: side stream handles weight prep + feature GEMM chain
    cudaEventRecord(ev[0], 0);
    cudaStreamWaitEvent(s1, ev[0], 0);

    prepw_kernel<<<(3 * 64 + 255) / 256, 256, 0, s1>>>(W1, wc1, 3, 64);
    prepw_kernel<<<(64 * 128 + 255) / 256, 256, 0, s1>>>(W2, wc2, 64, 128);
    prepw_kernel<<<(192 * 512 + 255) / 256, 256, 0, s1>>>(W3, wc3, 192, 512);
    gemm_kernel<<<dim3(1, NPTS / 128), 256, 0, s1>>>(x, wc1, qp, 3, 128);
    cudaEventRecord(ev[1], s1);

    // ---- stage 1 selection chain (default stream)
    sq_kernel<<<(NPTS + 255) / 256, 256>>>(x, sqp, 3);
    d2sym_kernel<<<symgrid, 256>>>(x, sqp, keys, 3);
    knn_kernel<<<NPTS, 256>>>(keys, idxp, x, sqp, 3);
    cudaStreamWaitEvent(0, ev[1], 0);
    gather_kernel<<<NPTS / 8, 128>>>(qp, idxp, b1, x1, 64, 1);
    cudaEventRecord(ev[2], 0);                 // x1 ready, qp free

    // side: gemm2 (reads x1, writes qp)
    cudaStreamWaitEvent(s1, ev[2], 0);
    gemm_kernel<<<dim3(2, NPTS / 128), 256, 0, s1>>>(x1, wc2, qp, 64, 256);
    cudaEventRecord(ev[3], s1);

    // ---- stage 2 selection chain
    sq_kernel<<<(NPTS + 255) / 256, 256>>>(x1, sqp, 64);
    d2sym_kernel<<<symgrid, 256>>>(x1, sqp, keys, 64);
    knn_kernel<<<NPTS, 256>>>(keys, idxp, x1, sqp, 64);
    cudaStreamWaitEvent(0, ev[3], 0);
    gather_kernel<<<NPTS / 4, 128>>>(qp, idxp, b2, x2, 128, 1);
    cudaEventRecord(ev[4], 0);                 // x2 ready, qp free

    // side: concat + gemm3
    cudaStreamWaitEvent(s1, ev[4], 0);
    concat_kernel<<<(NPTS * 48 + 255) / 256, 256, 0, s1>>>(x1, x2, xc);
    gemm_kernel<<<dim3(8, NPTS / 128), 256, 0, s1>>>(xc, wc3, qp, 192, 1024);
    cudaEventRecord(ev[5], s1);

    // ---- stage 3 selection chain
    sq_kernel<<<(NPTS + 255) / 256, 256>>>(x2, sqp, 128);
    d2sym_kernel<<<symgrid, 256>>>(x2, sqp, keys, 128);
    knn_kernel<<<NPTS, 256>>>(keys, idxp, x2, sqp, 128);
    cudaStreamWaitEvent(0, ev[5], 0);
    gather_kernel<<<NPTS, 128>>>(qp, idxp, b3, out, 512, 0);
}